// round 1
// baseline (speedup 1.0000x reference)
#include <cuda_runtime.h>
#include <cuda_bf16.h>

#define BB 8
#define NN 8192
#define MM 8192
#define DD 64
#define TILE 128
#define SXS 132   // padded k-major row stride (floats)

// Scratch (allocation-free rule: __device__ globals)
__device__ float    g_rowmin[BB * NN];
__device__ unsigned g_colmin[BB * MM];

__device__ __forceinline__ unsigned long long pack2(float v) {
    unsigned long long r;
    asm("mov.b64 %0, {%1, %1};" : "=l"(r) : "f"(v));
    return r;
}
__device__ __forceinline__ unsigned long long ffma2(unsigned long long a,
                                                    unsigned long long b,
                                                    unsigned long long c) {
    unsigned long long d;
    asm("fma.rn.f32x2 %0, %1, %2, %3;" : "=l"(d) : "l"(a), "l"(b), "l"(c));
    return d;
}
__device__ __forceinline__ float f2lo(unsigned long long p) {
    return __uint_as_float((unsigned)p);
}
__device__ __forceinline__ float f2hi(unsigned long long p) {
    return __uint_as_float((unsigned)(p >> 32));
}

__global__ void init_kernel() {
    int i = blockIdx.x * blockDim.x + threadIdx.x;
    if (i < BB * MM) g_colmin[i] = 0x7f800000u;  // +inf
}

extern __shared__ float smem[];

// Grid: (NN/TILE, BB). Block: 256 threads = 16(tx: j-groups) x 16(ty: i-groups).
// Each thread: 8 i x 8 j outputs, accumulated as 8x4 f32x2 pairs over j.
__global__ __launch_bounds__(256, 2) void chamfer_kernel(
    const float* __restrict__ X, const float* __restrict__ Y) {
    float* sx   = smem;                 // 64 * SXS
    float* sy   = sx + 64 * SXS;        // 64 * SXS
    float* sx2  = sy + 64 * SXS;        // TILE
    float* sy2  = sx2 + TILE;           // TILE
    float* scol = sy2 + TILE;           // 16 * TILE

    const int b   = blockIdx.y;
    const int it  = blockIdx.x;
    const int tid = threadIdx.x;
    const int tx  = tid & 15;
    const int ty  = tid >> 4;

    const float* xb = X + ((size_t)b * NN + (size_t)it * TILE) * DD;
    const float* yb = Y + (size_t)b * MM * DD;

    // ---- Load + transpose X tile into k-major smem ----
#pragma unroll
    for (int iter = 0; iter < 8; iter++) {
        int i = iter * 16 + ty;
        float4 v = *(const float4*)(xb + (size_t)i * DD + tx * 4);
        int k = tx * 4;
        sx[(k + 0) * SXS + i] = v.x;
        sx[(k + 1) * SXS + i] = v.y;
        sx[(k + 2) * SXS + i] = v.z;
        sx[(k + 3) * SXS + i] = v.w;
    }
    __syncthreads();
    if (tid < TILE) {
        float s = 0.f;
#pragma unroll
        for (int k = 0; k < DD; k++) {
            float v = sx[k * SXS + tid];
            s = fmaf(v, v, s);
        }
        sx2[tid] = s;
    }

    float rmin[8];
#pragma unroll
    for (int ii = 0; ii < 8; ii++) rmin[ii] = __int_as_float(0x7f800000);

    const float* xbase = sx + (ty << 3);
    const float* ybase = sy + (tx << 3);

    for (int jt = 0; jt < MM / TILE; jt++) {
        __syncthreads();  // protect sy / scol reuse (and sx2 on first iter)

        // ---- Load + transpose Y tile ----
        const float* yt = yb + (size_t)jt * TILE * DD;
#pragma unroll
        for (int iter = 0; iter < 8; iter++) {
            int j = iter * 16 + ty;
            float4 v = *(const float4*)(yt + (size_t)j * DD + tx * 4);
            int k = tx * 4;
            sy[(k + 0) * SXS + j] = v.x;
            sy[(k + 1) * SXS + j] = v.y;
            sy[(k + 2) * SXS + j] = v.z;
            sy[(k + 3) * SXS + j] = v.w;
        }
        __syncthreads();
        if (tid < TILE) {
            float s = 0.f;
#pragma unroll
            for (int k = 0; k < DD; k++) {
                float v = sy[k * SXS + tid];
                s = fmaf(v, v, s);
            }
            sy2[tid] = s;
        }
        __syncthreads();

        // ---- K-loop: 8x4 f32x2 accumulators of dot(x_i, y_j) ----
        unsigned long long acc[8][4];
#pragma unroll
        for (int ii = 0; ii < 8; ii++)
#pragma unroll
            for (int jp = 0; jp < 4; jp++) acc[ii][jp] = 0ull;

#pragma unroll 8
        for (int k = 0; k < DD; k++) {
            const float* xr = xbase + k * SXS;
            const float* yr = ybase + k * SXS;
            float4 xa  = *(const float4*)(xr);
            float4 xb4 = *(const float4*)(xr + 4);
            ulonglong2 y01 = *(const ulonglong2*)(yr);      // pairs (j0,j1),(j2,j3)
            ulonglong2 y23 = *(const ulonglong2*)(yr + 4);  // pairs (j4,j5),(j6,j7)
            unsigned long long yq[4] = {y01.x, y01.y, y23.x, y23.y};
            float xs[8] = {xa.x, xa.y, xa.z, xa.w, xb4.x, xb4.y, xb4.z, xb4.w};
#pragma unroll
            for (int ii = 0; ii < 8; ii++) {
                unsigned long long xp = pack2(xs[ii]);
#pragma unroll
                for (int jp = 0; jp < 4; jp++)
                    acc[ii][jp] = ffma2(xp, yq[jp], acc[ii][jp]);
            }
        }

        // ---- Epilogue: d2 = x2 + y2 - 2*dot ; update row/col mins ----
        float y2v[8];
#pragma unroll
        for (int jj = 0; jj < 8; jj++) y2v[jj] = sy2[(tx << 3) + jj];

        float cmin[8];
#pragma unroll
        for (int jj = 0; jj < 8; jj++) cmin[jj] = __int_as_float(0x7f800000);

#pragma unroll
        for (int ii = 0; ii < 8; ii++) {
            float x2 = sx2[(ty << 3) + ii];
#pragma unroll
            for (int jp = 0; jp < 4; jp++) {
                float dlo = fmaf(-2.f, f2lo(acc[ii][jp]), x2 + y2v[2 * jp]);
                float dhi = fmaf(-2.f, f2hi(acc[ii][jp]), x2 + y2v[2 * jp + 1]);
                rmin[ii] = fminf(rmin[ii], fminf(dlo, dhi));
                cmin[2 * jp]     = fminf(cmin[2 * jp], dlo);
                cmin[2 * jp + 1] = fminf(cmin[2 * jp + 1], dhi);
            }
        }

        // ---- Column-min: stage per-ty partials in smem, reduce, atomicMin ----
#pragma unroll
        for (int jj = 0; jj < 8; jj++) scol[ty * TILE + (tx << 3) + jj] = cmin[jj];
        __syncthreads();
        if (tid < TILE) {
            float m = __int_as_float(0x7f800000);
#pragma unroll
            for (int t = 0; t < 16; t++) m = fminf(m, scol[t * TILE + tid]);
            m = fmaxf(m, 0.f);
            atomicMin(&g_colmin[(size_t)b * MM + (size_t)jt * TILE + tid],
                      __float_as_uint(m));
        }
    }

    // ---- Row-min: butterfly reduce across the 16 tx lanes of each ty group ----
#pragma unroll
    for (int ii = 0; ii < 8; ii++) {
        float v = rmin[ii];
        v = fminf(v, __shfl_xor_sync(0xffffffffu, v, 1));
        v = fminf(v, __shfl_xor_sync(0xffffffffu, v, 2));
        v = fminf(v, __shfl_xor_sync(0xffffffffu, v, 4));
        v = fminf(v, __shfl_xor_sync(0xffffffffu, v, 8));
        rmin[ii] = v;
    }
    if (tx == 0) {
#pragma unroll
        for (int ii = 0; ii < 8; ii++)
            g_rowmin[(size_t)b * NN + (size_t)it * TILE + (ty << 3) + ii] =
                fmaxf(rmin[ii], 0.f);
    }
}

// Deterministic single-block final reduction: sum sqrt(min d2), scale.
__global__ void final_kernel(float* __restrict__ out) {
    __shared__ float red[1024];
    int tid = threadIdx.x;
    float s = 0.f;
    for (int i = tid; i < BB * NN; i += 1024) s += sqrtf(g_rowmin[i]);
    for (int i = tid; i < BB * MM; i += 1024)
        s += sqrtf(__uint_as_float(g_colmin[i]));
    red[tid] = s;
    __syncthreads();
    for (int off = 512; off > 0; off >>= 1) {
        if (tid < off) red[tid] += red[tid + off];
        __syncthreads();
    }
    if (tid == 0) out[0] = red[0] / ((float)BB * (float)MM);
}

extern "C" void kernel_launch(void* const* d_in, const int* in_sizes, int n_in,
                              void* d_out, int out_size) {
    const float* x = (const float*)d_in[0];
    const float* y = (const float*)d_in[1];
    float* out = (float*)d_out;

    const int smem_bytes = (64 * SXS * 2 + TILE * 2 + 16 * TILE) * (int)sizeof(float);
    cudaFuncSetAttribute(chamfer_kernel,
                         cudaFuncAttributeMaxDynamicSharedMemorySize, smem_bytes);

    init_kernel<<<(BB * MM + 255) / 256, 256>>>();
    chamfer_kernel<<<dim3(NN / TILE, BB), 256, smem_bytes>>>(x, y);
    final_kernel<<<1, 1024>>>(out);
}

// round 3
// speedup vs baseline: 3.4072x; 3.4072x over previous
#include <cuda_runtime.h>
#include <cstdint>

#define BB 8
#define NN 8192
#define MM 8192
#define DD 64
#define JT 128            // j-tile
#define NJT (MM / JT)     // 64
#define NTH 256
#define SAS 68            // padded row stride (floats)

// ---------------- scratch (__device__ globals; no allocs allowed) ----------
__device__ float    g_rowmin[BB * NN];
__device__ unsigned g_colmin[BB * MM];
__device__ float    g_x2[BB * NN];
__device__ float    g_y2[BB * MM];
__device__ float    g_xr[(size_t)BB * NN * DD];   // tf32-rounded X
__device__ float    g_yr[(size_t)BB * MM * DD];   // tf32-rounded Y

// ---------------- smem layout (floats) -------------------------------------
#define SA_F    0                       // X tile 128 x SAS
#define SB0_F   (128 * SAS)             // Y buf0
#define SB1_F   (SB0_F + 128 * SAS)     // Y buf1
#define SY2_F   (SB1_F + 128 * SAS)     // y2 tile (128)
#define SCOL_F  (SY2_F + 128)           // colmin stage 8x32 (256)
#define SROW_F  (SCOL_F + 256)          // rowmin stage 8x64 (512)
#define SMEM_F  (SROW_F + 512)
#define SMEM_BYTES (SMEM_F * 4)

__device__ __forceinline__ float tf32r(float x) {
    uint32_t u;
    asm("cvt.rna.tf32.f32 %0, %1;" : "=r"(u) : "f"(x));
    return __uint_as_float(u);
}

__device__ __forceinline__ void mma_tf32(float c[4], const uint32_t a[4],
                                         const uint32_t b[2]) {
    asm volatile(
        "mma.sync.aligned.m16n8k8.row.col.f32.tf32.tf32.f32 "
        "{%0,%1,%2,%3}, {%4,%5,%6,%7}, {%8,%9}, {%0,%1,%2,%3};"
        : "+f"(c[0]), "+f"(c[1]), "+f"(c[2]), "+f"(c[3])
        : "r"(a[0]), "r"(a[1]), "r"(a[2]), "r"(a[3]), "r"(b[0]), "r"(b[1]));
}

__device__ __forceinline__ void cp_async16(uint32_t sdst, const void* gsrc) {
    asm volatile("cp.async.cg.shared.global [%0], [%1], 16;"
                 :: "r"(sdst), "l"(gsrc) : "memory");
}
__device__ __forceinline__ uint32_t smem_u32(const void* p) {
    uint32_t a;
    asm("{ .reg .u64 t; cvta.to.shared.u64 t, %1; cvt.u32.u64 %0, t; }"
        : "=r"(a) : "l"(p));
    return a;
}

// ---------------- prep kernels ---------------------------------------------
__global__ void prep_y_kernel(const float* __restrict__ Y) {
    int r = blockIdx.x * blockDim.x + threadIdx.x;
    if (r >= BB * MM) return;
    const float4* src = (const float4*)(Y + (size_t)r * DD);
    float4* dst = (float4*)(g_yr + (size_t)r * DD);
    float s = 0.f;
#pragma unroll
    for (int q = 0; q < 16; q++) {
        float4 v = src[q];
        v.x = tf32r(v.x); v.y = tf32r(v.y); v.z = tf32r(v.z); v.w = tf32r(v.w);
        s = fmaf(v.x, v.x, fmaf(v.y, v.y, fmaf(v.z, v.z, fmaf(v.w, v.w, s))));
        dst[q] = v;
    }
    g_y2[r] = s;
    g_colmin[r] = 0x7f800000u;
}

__global__ void prep_x_kernel(const float* __restrict__ X) {
    int r = blockIdx.x * blockDim.x + threadIdx.x;
    if (r >= BB * NN) return;
    const float4* src = (const float4*)(X + (size_t)r * DD);
    float4* dst = (float4*)(g_xr + (size_t)r * DD);
    float s = 0.f;
#pragma unroll
    for (int q = 0; q < 16; q++) {
        float4 v = src[q];
        v.x = tf32r(v.x); v.y = tf32r(v.y); v.z = tf32r(v.z); v.w = tf32r(v.w);
        s = fmaf(v.x, v.x, fmaf(v.y, v.y, fmaf(v.z, v.z, fmaf(v.w, v.w, s))));
        dst[q] = v;
    }
    g_x2[r] = s;
}

// ---------------- main kernel ----------------------------------------------
extern __shared__ __align__(16) float smem[];

__global__ __launch_bounds__(NTH, 2) void chamfer_mma_kernel() {
    const int b = blockIdx.y, it = blockIdx.x;
    const int tid = threadIdx.x;
    const int wid = tid >> 5, lane = tid & 31;
    const int wi = wid >> 2, wj = wid & 3;      // warp tile: rows wi*64, cols wj*32
    const int r = lane >> 2, cth = lane & 3;

    // ---- X tile -> smem (row-major, stride SAS) ----
    const float* xg = g_xr + ((size_t)b * NN + (size_t)it * JT) * DD;
    {
        int row = tid >> 1, half = tid & 1;
        const float4* src = (const float4*)(xg + (size_t)row * DD + half * 32);
#pragma unroll
        for (int q = 0; q < 8; q++) {
            float4 v = src[q];
            *(float4*)(smem + SA_F + row * SAS + half * 32 + q * 4) = v;
        }
    }

    // ---- preload Y tile 0 ----
    const float* yg = g_yr + (size_t)b * MM * DD;
    const uint32_t sb_addr[2] = { smem_u32(smem + SB0_F), smem_u32(smem + SB1_F) };
    {
#pragma unroll
        for (int itr = 0; itr < 8; itr++) {
            int c = tid + itr * NTH;           // 2048 16B chunks
            int row = c >> 4, q = c & 15;
            cp_async16(sb_addr[0] + (row * SAS + q * 4) * 4,
                       yg + (size_t)row * DD + q * 4);
        }
        asm volatile("cp.async.commit_group;" ::: "memory");
    }

    // ---- x2 regs (8 rows per thread) ----
    float x2r[4][2];
#pragma unroll
    for (int mt = 0; mt < 4; mt++)
#pragma unroll
        for (int h = 0; h < 2; h++)
            x2r[mt][h] = g_x2[(size_t)b * NN + (size_t)it * JT +
                              wi * 64 + mt * 16 + r + h * 8];

    float rmin[4][2];
#pragma unroll
    for (int mt = 0; mt < 4; mt++) { rmin[mt][0] = 1e30f; rmin[mt][1] = 1e30f; }

    const uint32_t* sAu = (const uint32_t*)(smem + SA_F);

    for (int jt = 0; jt < NJT; jt++) {
        const int cur = jt & 1;
        asm volatile("cp.async.wait_group 0;" ::: "memory");
        __syncthreads();                       // Y(jt) resident; buf cur^1 free

        // stage y2 for this jt
        if (tid < JT)
            smem[SY2_F + tid] = g_y2[(size_t)b * MM + (size_t)jt * JT + tid];

        // prefetch Y(jt+1)
        if (jt + 1 < NJT) {
            const float* yn = yg + (size_t)(jt + 1) * JT * DD;
#pragma unroll
            for (int itr = 0; itr < 8; itr++) {
                int c = tid + itr * NTH;
                int row = c >> 4, q = c & 15;
                cp_async16(sb_addr[cur ^ 1] + (row * SAS + q * 4) * 4,
                           yn + (size_t)row * DD + q * 4);
            }
            asm volatile("cp.async.commit_group;" ::: "memory");
        }

        // ---- k-loop: 4x4 m16n8k8 mmas x 8 ksteps ----
        float acc[4][4][4];
#pragma unroll
        for (int mt = 0; mt < 4; mt++)
#pragma unroll
            for (int nt = 0; nt < 4; nt++)
#pragma unroll
                for (int q = 0; q < 4; q++) acc[mt][nt][q] = 0.f;

        const uint32_t* sBu =
            (const uint32_t*)(smem + (cur ? SB1_F : SB0_F));
#pragma unroll
        for (int ks = 0; ks < 8; ks++) {
            const int cb = ks * 8 + cth;
            uint32_t a[4][4], bb[4][2];
#pragma unroll
            for (int mt = 0; mt < 4; mt++) {
                int base = (wi * 64 + mt * 16 + r) * SAS + cb;
                a[mt][0] = sAu[base];
                a[mt][1] = sAu[base + 8 * SAS];
                a[mt][2] = sAu[base + 4];
                a[mt][3] = sAu[base + 8 * SAS + 4];
            }
#pragma unroll
            for (int nt = 0; nt < 4; nt++) {
                int base = (wj * 32 + nt * 8 + r) * SAS + cb;
                bb[nt][0] = sBu[base];
                bb[nt][1] = sBu[base + 4];
            }
#pragma unroll
            for (int mt = 0; mt < 4; mt++)
#pragma unroll
                for (int nt = 0; nt < 4; nt++)
                    mma_tf32(acc[mt][nt], a[mt], bb[nt]);
        }

        __syncthreads();                       // sy2 visible

        // ---- epilogue ----
        float cslot[4][2];
#pragma unroll
        for (int nt = 0; nt < 4; nt++) { cslot[nt][0] = 1e30f; cslot[nt][1] = 1e30f; }

#pragma unroll
        for (int nt = 0; nt < 4; nt++) {
            float2 y2p = *(const float2*)(smem + SY2_F + wj * 32 + nt * 8 + 2 * cth);
#pragma unroll
            for (int mt = 0; mt < 4; mt++) {
                float c0 = acc[mt][nt][0], c1 = acc[mt][nt][1];
                float c2 = acc[mt][nt][2], c3 = acc[mt][nt][3];
                rmin[mt][0] = fminf(rmin[mt][0],
                    fminf(fmaf(-2.f, c0, y2p.x), fmaf(-2.f, c1, y2p.y)));
                rmin[mt][1] = fminf(rmin[mt][1],
                    fminf(fmaf(-2.f, c2, y2p.x), fmaf(-2.f, c3, y2p.y)));
                cslot[nt][0] = fminf(cslot[nt][0],
                    fminf(fmaf(-2.f, c0, x2r[mt][0]), fmaf(-2.f, c2, x2r[mt][1])));
                cslot[nt][1] = fminf(cslot[nt][1],
                    fminf(fmaf(-2.f, c1, x2r[mt][0]), fmaf(-2.f, c3, x2r[mt][1])));
            }
        }
        // reduce col slots over the r-bits of the lane (lane = 4r + cth)
#pragma unroll
        for (int m = 4; m <= 16; m <<= 1)
#pragma unroll
            for (int nt = 0; nt < 4; nt++) {
                cslot[nt][0] = fminf(cslot[nt][0],
                                     __shfl_xor_sync(0xffffffffu, cslot[nt][0], m));
                cslot[nt][1] = fminf(cslot[nt][1],
                                     __shfl_xor_sync(0xffffffffu, cslot[nt][1], m));
            }
        if (r == 0) {
#pragma unroll
            for (int nt = 0; nt < 4; nt++) {
                smem[SCOL_F + wid * 32 + nt * 8 + 2 * cth]     = cslot[nt][0];
                smem[SCOL_F + wid * 32 + nt * 8 + 2 * cth + 1] = cslot[nt][1];
            }
        }
        __syncthreads();

        if (tid < JT) {
            float m = fminf(smem[SCOL_F + tid], smem[SCOL_F + 128 + tid]);
            float d2c = fmaxf(smem[SY2_F + tid] + m, 0.f);
            atomicMin(&g_colmin[(size_t)b * MM + (size_t)jt * JT + tid],
                      __float_as_uint(d2c));
        }
    }

    // ---- rowmin finalize ----
#pragma unroll
    for (int mt = 0; mt < 4; mt++)
#pragma unroll
        for (int h = 0; h < 2; h++) {
            float v = rmin[mt][h];
            v = fminf(v, __shfl_xor_sync(0xffffffffu, v, 1));
            v = fminf(v, __shfl_xor_sync(0xffffffffu, v, 2));
            if (cth == 0)
                smem[SROW_F + wid * 64 + mt * 16 + r + h * 8] = v;
        }
    __syncthreads();
    if (tid < JT) {
        int wi2 = tid >> 6, rl = tid & 63;
        float m =          smem[SROW_F + (wi2 * 4 + 0) * 64 + rl];
        m = fminf(m, smem[SROW_F + (wi2 * 4 + 1) * 64 + rl]);
        m = fminf(m, smem[SROW_F + (wi2 * 4 + 2) * 64 + rl]);
        m = fminf(m, smem[SROW_F + (wi2 * 4 + 3) * 64 + rl]);
        size_t row = (size_t)b * NN + (size_t)it * JT + wi2 * 64 + rl;
        g_rowmin[row] = fmaxf(g_x2[row] + m, 0.f);
    }
}

// ---------------- final reduction ------------------------------------------
__global__ void final_kernel(float* __restrict__ out) {
    __shared__ float red[1024];
    int tid = threadIdx.x;
    float s = 0.f;
    for (int i = tid; i < BB * NN; i += 1024) s += sqrtf(g_rowmin[i]);
    for (int i = tid; i < BB * MM; i += 1024)
        s += sqrtf(__uint_as_float(g_colmin[i]));
    red[tid] = s;
    __syncthreads();
    for (int off = 512; off > 0; off >>= 1) {
        if (tid < off) red[tid] += red[tid + off];
        __syncthreads();
    }
    if (tid == 0) out[0] = red[0] / ((float)BB * (float)MM);
}

extern "C" void kernel_launch(void* const* d_in, const int* in_sizes, int n_in,
                              void* d_out, int out_size) {
    const float* x = (const float*)d_in[0];
    const float* y = (const float*)d_in[1];
    float* out = (float*)d_out;

    cudaFuncSetAttribute(chamfer_mma_kernel,
                         cudaFuncAttributeMaxDynamicSharedMemorySize, SMEM_BYTES);

    prep_y_kernel<<<(BB * MM + 255) / 256, 256>>>(y);
    prep_x_kernel<<<(BB * NN + 255) / 256, 256>>>(x);
    chamfer_mma_kernel<<<dim3(NN / JT, BB), NTH, SMEM_BYTES>>>();
    final_kernel<<<1, 1024>>>(out);
}

// round 4
// speedup vs baseline: 5.9444x; 1.7447x over previous
#include <cuda_runtime.h>
#include <cuda_fp16.h>
#include <cstdint>

#define BB 8
#define NN 8192
#define MM 8192
#define DD 64
#define JT 128            // j-tile
#define NJT (MM / JT)     // 64
#define NTH 256
#define RS 72             // padded row stride in halves (144 B)

// ---------------- scratch (__device__ globals) ------------------------------
__device__ float    g_rowmin[BB * NN];
__device__ unsigned g_colmin[BB * MM];
__device__ float    g_x2[BB * NN];
__device__ float    g_y2[BB * MM];
__device__ __half   g_xh[(size_t)BB * NN * DD];
__device__ __half   g_yh[(size_t)BB * MM * DD];
__device__ float    g_partial[128];

// ---------------- smem layout ----------------------------------------------
// halves region then float region
#define SA_H    0                        // X tile 128 x RS halves
#define SB0_H   (128 * RS)               // Y buf0
#define SB1_H   (SB0_H + 128 * RS)       // Y buf1
#define HALVES  (SB1_H + 128 * RS)       // 27648 halves
#define SY2_F   (HALVES / 2)             // float idx; 128 f
#define SCOL_F  (SY2_F + 128)            // 256 f
#define SROW_F  (SCOL_F + 256)           // 512 f
#define SMEM_F  (SROW_F + 512)
#define SMEM_BYTES (SMEM_F * 4)

__device__ __forceinline__ uint32_t smem_u32(const void* p) {
    uint32_t a;
    asm("{ .reg .u64 t; cvta.to.shared.u64 t, %1; cvt.u32.u64 %0, t; }"
        : "=r"(a) : "l"(p));
    return a;
}
__device__ __forceinline__ void cp_async16(uint32_t sdst, const void* gsrc) {
    asm volatile("cp.async.cg.shared.global [%0], [%1], 16;"
                 :: "r"(sdst), "l"(gsrc) : "memory");
}
__device__ __forceinline__ void ldmatrix_x4(uint32_t r[4], uint32_t addr) {
    asm volatile("ldmatrix.sync.aligned.m8n8.x4.shared.b16 {%0,%1,%2,%3}, [%4];"
                 : "=r"(r[0]), "=r"(r[1]), "=r"(r[2]), "=r"(r[3]) : "r"(addr));
}
__device__ __forceinline__ void ldmatrix_x2(uint32_t r[2], uint32_t addr) {
    asm volatile("ldmatrix.sync.aligned.m8n8.x2.shared.b16 {%0,%1}, [%2];"
                 : "=r"(r[0]), "=r"(r[1]) : "r"(addr));
}
__device__ __forceinline__ void mma_f16(float c[4], const uint32_t a[4],
                                        const uint32_t b[2]) {
    asm volatile(
        "mma.sync.aligned.m16n8k16.row.col.f32.f16.f16.f32 "
        "{%0,%1,%2,%3}, {%4,%5,%6,%7}, {%8,%9}, {%0,%1,%2,%3};"
        : "+f"(c[0]), "+f"(c[1]), "+f"(c[2]), "+f"(c[3])
        : "r"(a[0]), "r"(a[1]), "r"(a[2]), "r"(a[3]), "r"(b[0]), "r"(b[1]));
}

// ---------------- prep kernels ---------------------------------------------
__global__ void prep_y_kernel(const float* __restrict__ Y) {
    int r = blockIdx.x * blockDim.x + threadIdx.x;
    if (r >= BB * MM) return;
    const float4* src = (const float4*)(Y + (size_t)r * DD);
    __half* dst = g_yh + (size_t)r * DD;
    float s = 0.f;
#pragma unroll
    for (int q = 0; q < 16; q++) {
        float4 v = src[q];
        __half h0 = __float2half_rn(v.x), h1 = __float2half_rn(v.y);
        __half h2 = __float2half_rn(v.z), h3 = __float2half_rn(v.w);
        float f0 = __half2float(h0), f1 = __half2float(h1);
        float f2 = __half2float(h2), f3 = __half2float(h3);
        s = fmaf(f0, f0, fmaf(f1, f1, fmaf(f2, f2, fmaf(f3, f3, s))));
        __half2* d2 = (__half2*)(dst + q * 4);
        d2[0] = __halves2half2(h0, h1);
        d2[1] = __halves2half2(h2, h3);
    }
    g_y2[r] = s;
    g_colmin[r] = 0x7f800000u;
}

__global__ void prep_x_kernel(const float* __restrict__ X) {
    int r = blockIdx.x * blockDim.x + threadIdx.x;
    if (r >= BB * NN) return;
    const float4* src = (const float4*)(X + (size_t)r * DD);
    __half* dst = g_xh + (size_t)r * DD;
    float s = 0.f;
#pragma unroll
    for (int q = 0; q < 16; q++) {
        float4 v = src[q];
        __half h0 = __float2half_rn(v.x), h1 = __float2half_rn(v.y);
        __half h2 = __float2half_rn(v.z), h3 = __float2half_rn(v.w);
        float f0 = __half2float(h0), f1 = __half2float(h1);
        float f2 = __half2float(h2), f3 = __half2float(h3);
        s = fmaf(f0, f0, fmaf(f1, f1, fmaf(f2, f2, fmaf(f3, f3, s))));
        __half2* d2 = (__half2*)(dst + q * 4);
        d2[0] = __halves2half2(h0, h1);
        d2[1] = __halves2half2(h2, h3);
    }
    g_x2[r] = s;
}

// ---------------- main kernel ----------------------------------------------
extern __shared__ __align__(16) float smem[];

__global__ __launch_bounds__(NTH, 2) void chamfer_mma_kernel() {
    const int b = blockIdx.y, it = blockIdx.x;
    const int tid = threadIdx.x;
    const int wid = tid >> 5, lane = tid & 31;
    const int wi = wid >> 2, wj = wid & 3;      // warptile rows wi*64, cols wj*32
    const int r = lane >> 2, cth = lane & 3;

    __half* sh = (__half*)smem;
    const uint32_t sbase = smem_u32(smem);

    // ---- X tile -> smem via cp.async (1024 16B chunks) ----
    const __half* xg = g_xh + ((size_t)b * NN + (size_t)it * JT) * DD;
#pragma unroll
    for (int itr = 0; itr < 4; itr++) {
        int c = tid + itr * NTH;
        int row = c >> 3, q = c & 7;
        cp_async16(sbase + SA_H * 2 + row * (RS * 2) + q * 16,
                   xg + (size_t)row * DD + q * 8);
    }
    // ---- Y tile 0 ----
    const __half* yg = g_yh + (size_t)b * MM * DD;
#pragma unroll
    for (int itr = 0; itr < 4; itr++) {
        int c = tid + itr * NTH;
        int row = c >> 3, q = c & 7;
        cp_async16(sbase + SB0_H * 2 + row * (RS * 2) + q * 16,
                   yg + (size_t)row * DD + q * 8);
    }
    asm volatile("cp.async.commit_group;" ::: "memory");

    // ---- x2 regs (8 rows per thread) ----
    float x2r[4][2];
#pragma unroll
    for (int mt = 0; mt < 4; mt++)
#pragma unroll
        for (int h = 0; h < 2; h++)
            x2r[mt][h] = g_x2[(size_t)b * NN + (size_t)it * JT +
                              wi * 64 + mt * 16 + r + h * 8];

    float rmin[4][2];
#pragma unroll
    for (int mt = 0; mt < 4; mt++) { rmin[mt][0] = 1e30f; rmin[mt][1] = 1e30f; }

    // ldmatrix per-lane base addresses (bytes)
    const int amat = lane >> 3;                   // 0..3
    const uint32_t a_base = sbase + SA_H * 2 +
        (uint32_t)(wi * 64 + (lane & 7) + (amat & 1) * 8) * (RS * 2) +
        (uint32_t)(amat >> 1) * 16;
    const uint32_t b_off = (uint32_t)(wj * 32 + (lane & 7)) * (RS * 2) +
                           (uint32_t)((lane >> 3) & 1) * 16;
    const uint32_t b_base[2] = { sbase + SB0_H * 2 + b_off,
                                 sbase + SB1_H * 2 + b_off };

    for (int jt = 0; jt < NJT; jt++) {
        const int cur = jt & 1;
        asm volatile("cp.async.wait_group 0;" ::: "memory");
        __syncthreads();                       // Y(jt) (and X on jt==0) resident

        if (tid < JT)
            smem[SY2_F + tid] = g_y2[(size_t)b * MM + (size_t)jt * JT + tid];

        // prefetch Y(jt+1)
        if (jt + 1 < NJT) {
            const __half* yn = yg + (size_t)(jt + 1) * JT * DD;
            uint32_t dstb = sbase + (cur ? SB0_H : SB1_H) * 2;
#pragma unroll
            for (int itr = 0; itr < 4; itr++) {
                int c = tid + itr * NTH;
                int row = c >> 3, q = c & 7;
                cp_async16(dstb + row * (RS * 2) + q * 16,
                           yn + (size_t)row * DD + q * 8);
            }
            asm volatile("cp.async.commit_group;" ::: "memory");
        }

        // ---- k-loop: 4 ksteps of m16n8k16, 4x4 warptile ----
        float acc[4][4][4];
#pragma unroll
        for (int mt = 0; mt < 4; mt++)
#pragma unroll
            for (int nt = 0; nt < 4; nt++)
#pragma unroll
                for (int q = 0; q < 4; q++) acc[mt][nt][q] = 0.f;

        const uint32_t bb0 = b_base[cur];
#pragma unroll
        for (int ks = 0; ks < 4; ks++) {
            uint32_t a[4][4], bbr[4][2];
#pragma unroll
            for (int mt = 0; mt < 4; mt++)
                ldmatrix_x4(a[mt], a_base + mt * 16 * (RS * 2) + ks * 32);
#pragma unroll
            for (int nt = 0; nt < 4; nt++)
                ldmatrix_x2(bbr[nt], bb0 + nt * 8 * (RS * 2) + ks * 32);
#pragma unroll
            for (int mt = 0; mt < 4; mt++)
#pragma unroll
                for (int nt = 0; nt < 4; nt++)
                    mma_f16(acc[mt][nt], a[mt], bbr[nt]);
        }

        __syncthreads();                       // sy2 visible

        // ---- epilogue: row/col mins ----
        float cslot[4][2];
#pragma unroll
        for (int nt = 0; nt < 4; nt++) { cslot[nt][0] = 1e30f; cslot[nt][1] = 1e30f; }

#pragma unroll
        for (int nt = 0; nt < 4; nt++) {
            float2 y2p = *(const float2*)(smem + SY2_F + wj * 32 + nt * 8 + 2 * cth);
#pragma unroll
            for (int mt = 0; mt < 4; mt++) {
                float c0 = acc[mt][nt][0], c1 = acc[mt][nt][1];
                float c2 = acc[mt][nt][2], c3 = acc[mt][nt][3];
                rmin[mt][0] = fminf(rmin[mt][0],
                    fminf(fmaf(-2.f, c0, y2p.x), fmaf(-2.f, c1, y2p.y)));
                rmin[mt][1] = fminf(rmin[mt][1],
                    fminf(fmaf(-2.f, c2, y2p.x), fmaf(-2.f, c3, y2p.y)));
                cslot[nt][0] = fminf(cslot[nt][0],
                    fminf(fmaf(-2.f, c0, x2r[mt][0]), fmaf(-2.f, c2, x2r[mt][1])));
                cslot[nt][1] = fminf(cslot[nt][1],
                    fminf(fmaf(-2.f, c1, x2r[mt][0]), fmaf(-2.f, c3, x2r[mt][1])));
            }
        }
#pragma unroll
        for (int m = 4; m <= 16; m <<= 1)
#pragma unroll
            for (int nt = 0; nt < 4; nt++) {
                cslot[nt][0] = fminf(cslot[nt][0],
                                     __shfl_xor_sync(0xffffffffu, cslot[nt][0], m));
                cslot[nt][1] = fminf(cslot[nt][1],
                                     __shfl_xor_sync(0xffffffffu, cslot[nt][1], m));
            }
        if (r == 0) {
#pragma unroll
            for (int nt = 0; nt < 4; nt++) {
                smem[SCOL_F + wid * 32 + nt * 8 + 2 * cth]     = cslot[nt][0];
                smem[SCOL_F + wid * 32 + nt * 8 + 2 * cth + 1] = cslot[nt][1];
            }
        }
        __syncthreads();

        if (tid < JT) {
            float m = fminf(smem[SCOL_F + tid], smem[SCOL_F + 128 + tid]);
            float d2c = fmaxf(smem[SY2_F + tid] + m, 0.f);
            atomicMin(&g_colmin[(size_t)b * MM + (size_t)jt * JT + tid],
                      __float_as_uint(d2c));
        }
    }

    // ---- rowmin finalize ----
#pragma unroll
    for (int mt = 0; mt < 4; mt++)
#pragma unroll
        for (int h = 0; h < 2; h++) {
            float v = rmin[mt][h];
            v = fminf(v, __shfl_xor_sync(0xffffffffu, v, 1));
            v = fminf(v, __shfl_xor_sync(0xffffffffu, v, 2));
            if (cth == 0)
                smem[SROW_F + wid * 64 + mt * 16 + r + h * 8] = v;
        }
    __syncthreads();
    if (tid < JT) {
        int wi2 = tid >> 6, rl = tid & 63;
        float m =          smem[SROW_F + (wi2 * 4 + 0) * 64 + rl];
        m = fminf(m, smem[SROW_F + (wi2 * 4 + 1) * 64 + rl]);
        m = fminf(m, smem[SROW_F + (wi2 * 4 + 2) * 64 + rl]);
        m = fminf(m, smem[SROW_F + (wi2 * 4 + 3) * 64 + rl]);
        size_t row = (size_t)b * NN + (size_t)it * JT + wi2 * 64 + rl;
        g_rowmin[row] = fmaxf(g_x2[row] + m, 0.f);
    }
}

// ---------------- final reduction (parallel, deterministic) ----------------
__global__ void partial_kernel() {
    __shared__ float red[256];
    const int tid = threadIdx.x, blk = blockIdx.x;
    // 131072 total elems, 128 blocks, 1024 per block, 4 per thread
    float s = 0.f;
#pragma unroll
    for (int q = 0; q < 4; q++) {
        int i = blk * 1024 + q * 256 + tid;
        if (i < BB * NN) s += sqrtf(g_rowmin[i]);
        else s += sqrtf(__uint_as_float(g_colmin[i - BB * NN]));
    }
    red[tid] = s;
    __syncthreads();
    for (int off = 128; off > 0; off >>= 1) {
        if (tid < off) red[tid] += red[tid + off];
        __syncthreads();
    }
    if (tid == 0) g_partial[blk] = red[0];
}

__global__ void final_kernel(float* __restrict__ out) {
    __shared__ float red[128];
    int tid = threadIdx.x;
    red[tid] = g_partial[tid];
    __syncthreads();
    for (int off = 64; off > 0; off >>= 1) {
        if (tid < off) red[tid] += red[tid + off];
        __syncthreads();
    }
    if (tid == 0) out[0] = red[0] / ((float)BB * (float)MM);
}

extern "C" void kernel_launch(void* const* d_in, const int* in_sizes, int n_in,
                              void* d_out, int out_size) {
    const float* x = (const float*)d_in[0];
    const float* y = (const float*)d_in[1];
    float* out = (float*)d_out;

    cudaFuncSetAttribute(chamfer_mma_kernel,
                         cudaFuncAttributeMaxDynamicSharedMemorySize, SMEM_BYTES);

    prep_y_kernel<<<(BB * MM + 255) / 256, 256>>>(y);
    prep_x_kernel<<<(BB * NN + 255) / 256, 256>>>(x);
    chamfer_mma_kernel<<<dim3(NN / JT, BB), NTH, SMEM_BYTES>>>();
    partial_kernel<<<128, 256>>>();
    final_kernel<<<1, 128>>>(out);
}

// round 6
// speedup vs baseline: 6.4682x; 1.0881x over previous
#include <cuda_runtime.h>
#include <cuda_fp16.h>
#include <cstdint>

#define BB 8
#define NN 8192
#define MM 8192
#define DD 64
#define JT 128            // j-tile width
#define NJT (MM / JT)     // 64
#define JQ 16             // j-tiles per CTA (quarter of the j range)
#define NTH 256
#define RS 72             // padded row stride in halves (144 B)

// ---------------- scratch (__device__ globals) ------------------------------
__device__ unsigned g_rowmin[BB * NN];
__device__ unsigned g_colmin[BB * MM];
__device__ float    g_x2[BB * NN];
__device__ float    g_y2[BB * MM];
__device__ __half   g_xh[(size_t)BB * NN * DD];
__device__ __half   g_yh[(size_t)BB * MM * DD];
__device__ float    g_partial[128];

// ---------------- smem layout ----------------------------------------------
#define SA_H    0                        // X tile 128 x RS halves
#define SB0_H   (128 * RS)               // Y buf0
#define SB1_H   (SB0_H + 128 * RS)       // Y buf1
#define HALVES  (SB1_H + 128 * RS)       // 27648 halves
#define SROW_F  (HALVES / 2)             // rowmin stage 8x64 (512 f)
#define SMEM_F  (SROW_F + 512)
#define SMEM_BYTES (SMEM_F * 4)

__device__ __forceinline__ uint32_t smem_u32(const void* p) {
    uint32_t a;
    asm("{ .reg .u64 t; cvta.to.shared.u64 t, %1; cvt.u32.u64 %0, t; }"
        : "=r"(a) : "l"(p));
    return a;
}
__device__ __forceinline__ void cp_async16(uint32_t sdst, const void* gsrc) {
    asm volatile("cp.async.cg.shared.global [%0], [%1], 16;"
                 :: "r"(sdst), "l"(gsrc) : "memory");
}
__device__ __forceinline__ void ldmatrix_x4(uint32_t r[4], uint32_t addr) {
    asm volatile("ldmatrix.sync.aligned.m8n8.x4.shared.b16 {%0,%1,%2,%3}, [%4];"
                 : "=r"(r[0]), "=r"(r[1]), "=r"(r[2]), "=r"(r[3]) : "r"(addr));
}
__device__ __forceinline__ void ldmatrix_x2(uint32_t r[2], uint32_t addr) {
    asm volatile("ldmatrix.sync.aligned.m8n8.x2.shared.b16 {%0,%1}, [%2];"
                 : "=r"(r[0]), "=r"(r[1]) : "r"(addr));
}
__device__ __forceinline__ void mma_f16(float c[4], const uint32_t a[4],
                                        const uint32_t b[2]) {
    asm volatile(
        "mma.sync.aligned.m16n8k16.row.col.f32.f16.f16.f32 "
        "{%0,%1,%2,%3}, {%4,%5,%6,%7}, {%8,%9}, {%0,%1,%2,%3};"
        : "+f"(c[0]), "+f"(c[1]), "+f"(c[2]), "+f"(c[3])
        : "r"(a[0]), "r"(a[1]), "r"(a[2]), "r"(a[3]), "r"(b[0]), "r"(b[1]));
}
// packed f32x2 helpers
__device__ __forceinline__ unsigned long long packf2(float lo, float hi) {
    unsigned long long r;
    asm("mov.b64 %0, {%1, %2};" : "=l"(r) : "f"(lo), "f"(hi));
    return r;
}
__device__ __forceinline__ unsigned long long ffma2(unsigned long long a,
                                                    unsigned long long b,
                                                    unsigned long long c) {
    unsigned long long d;
    asm("fma.rn.f32x2 %0, %1, %2, %3;" : "=l"(d) : "l"(a), "l"(b), "l"(c));
    return d;
}
__device__ __forceinline__ float f2lo(unsigned long long p) {
    return __uint_as_float((unsigned)p);
}
__device__ __forceinline__ float f2hi(unsigned long long p) {
    return __uint_as_float((unsigned)(p >> 32));
}
#define NEG2PK 0xC0000000C0000000ULL   // {-2.f, -2.f}

// ---------------- prep kernels ---------------------------------------------
__global__ void prep_y_kernel(const float* __restrict__ Y) {
    int r = blockIdx.x * blockDim.x + threadIdx.x;
    if (r >= BB * MM) return;
    const float4* src = (const float4*)(Y + (size_t)r * DD);
    __half* dst = g_yh + (size_t)r * DD;
    float s = 0.f;
#pragma unroll
    for (int q = 0; q < 16; q++) {
        float4 v = src[q];
        __half h0 = __float2half_rn(v.x), h1 = __float2half_rn(v.y);
        __half h2 = __float2half_rn(v.z), h3 = __float2half_rn(v.w);
        float f0 = __half2float(h0), f1 = __half2float(h1);
        float f2 = __half2float(h2), f3 = __half2float(h3);
        s = fmaf(f0, f0, fmaf(f1, f1, fmaf(f2, f2, fmaf(f3, f3, s))));
        __half2* d2 = (__half2*)(dst + q * 4);
        d2[0] = __halves2half2(h0, h1);
        d2[1] = __halves2half2(h2, h3);
    }
    g_y2[r] = s;
    g_colmin[r] = 0x7f800000u;
}

__global__ void prep_x_kernel(const float* __restrict__ X) {
    int r = blockIdx.x * blockDim.x + threadIdx.x;
    if (r >= BB * NN) return;
    const float4* src = (const float4*)(X + (size_t)r * DD);
    __half* dst = g_xh + (size_t)r * DD;
    float s = 0.f;
#pragma unroll
    for (int q = 0; q < 16; q++) {
        float4 v = src[q];
        __half h0 = __float2half_rn(v.x), h1 = __float2half_rn(v.y);
        __half h2 = __float2half_rn(v.z), h3 = __float2half_rn(v.w);
        float f0 = __half2float(h0), f1 = __half2float(h1);
        float f2 = __half2float(h2), f3 = __half2float(h3);
        s = fmaf(f0, f0, fmaf(f1, f1, fmaf(f2, f2, fmaf(f3, f3, s))));
        __half2* d2 = (__half2*)(dst + q * 4);
        d2[0] = __halves2half2(h0, h1);
        d2[1] = __halves2half2(h2, h3);
    }
    g_x2[r] = s;
    g_rowmin[r] = 0x7f800000u;
}

// ---------------- main kernel ----------------------------------------------
extern __shared__ __align__(16) float smem[];

__global__ __launch_bounds__(NTH, 2) void chamfer_mma_kernel() {
    const int b = blockIdx.y, it = blockIdx.x;
    const int jt0 = blockIdx.z * JQ;
    const int tid = threadIdx.x;
    const int wid = tid >> 5, lane = tid & 31;
    const int wi = wid >> 2, wj = wid & 3;      // warptile rows wi*64, cols wj*32
    const int r = lane >> 2, cth = lane & 3;

    const uint32_t sbase = smem_u32(smem);

    // ---- X tile + Y(jt0) -> smem via cp.async ----
    const __half* xg = g_xh + ((size_t)b * NN + (size_t)it * JT) * DD;
    const __half* yg = g_yh + (size_t)b * MM * DD;
#pragma unroll
    for (int itr = 0; itr < 4; itr++) {
        int c = tid + itr * NTH;
        int row = c >> 3, q = c & 7;
        cp_async16(sbase + SA_H * 2 + row * (RS * 2) + q * 16,
                   xg + (size_t)row * DD + q * 8);
    }
#pragma unroll
    for (int itr = 0; itr < 4; itr++) {
        int c = tid + itr * NTH;
        int row = c >> 3, q = c & 7;
        cp_async16(sbase + SB0_H * 2 + row * (RS * 2) + q * 16,
                   yg + ((size_t)jt0 * JT + row) * DD + q * 8);
    }
    asm volatile("cp.async.commit_group;" ::: "memory");

    // ---- x2 regs (8 rows per thread) ----
    float x2r[4][2];
#pragma unroll
    for (int mt = 0; mt < 4; mt++)
#pragma unroll
        for (int h = 0; h < 2; h++)
            x2r[mt][h] = g_x2[(size_t)b * NN + (size_t)it * JT +
                              wi * 64 + mt * 16 + r + h * 8];

    float rmin[4][2];
#pragma unroll
    for (int mt = 0; mt < 4; mt++) { rmin[mt][0] = 1e30f; rmin[mt][1] = 1e30f; }

    // ldmatrix per-lane base addresses (bytes)
    const int amat = lane >> 3;
    const uint32_t a_base = sbase + SA_H * 2 +
        (uint32_t)(wi * 64 + (lane & 7) + (amat & 1) * 8) * (RS * 2) +
        (uint32_t)(amat >> 1) * 16;
    const uint32_t b_off = (uint32_t)(wj * 32 + (lane & 7)) * (RS * 2) +
                           (uint32_t)((lane >> 3) & 1) * 16;
    const uint32_t b_base[2] = { sbase + SB0_H * 2 + b_off,
                                 sbase + SB1_H * 2 + b_off };

    const float* y2g = g_y2 + (size_t)b * MM;
    unsigned* colg = g_colmin + (size_t)b * MM;

    for (int jj = 0; jj < JQ; jj++) {
        const int jt = jt0 + jj;
        const int cur = jj & 1;
        asm volatile("cp.async.wait_group 0;" ::: "memory");
        __syncthreads();                       // Y(jt) resident; other buf free

        // prefetch Y(jt+1)
        if (jj + 1 < JQ) {
            const __half* yn = yg + (size_t)(jt + 1) * JT * DD;
            uint32_t dstb = sbase + (cur ? SB0_H : SB1_H) * 2;
#pragma unroll
            for (int itr = 0; itr < 4; itr++) {
                int c = tid + itr * NTH;
                int row = c >> 3, q = c & 7;
                cp_async16(dstb + row * (RS * 2) + q * 16,
                           yn + (size_t)row * DD + q * 8);
            }
            asm volatile("cp.async.commit_group;" ::: "memory");
        }

        // y2 for this warp's columns (latency hidden under k-loop)
        float2 y2s[4];
#pragma unroll
        for (int nt = 0; nt < 4; nt++)
            y2s[nt] = __ldg((const float2*)(y2g + jt * JT + wj * 32 + nt * 8 + 2 * cth));

        // ---- k-loop: 4 ksteps of m16n8k16, 4x4 warptile ----
        float acc[4][4][4];
#pragma unroll
        for (int mt = 0; mt < 4; mt++)
#pragma unroll
            for (int nt = 0; nt < 4; nt++)
#pragma unroll
                for (int q = 0; q < 4; q++) acc[mt][nt][q] = 0.f;

        const uint32_t bb0 = b_base[cur];
#pragma unroll
        for (int ks = 0; ks < 4; ks++) {
            uint32_t a[4][4], bbr[4][2];
#pragma unroll
            for (int mt = 0; mt < 4; mt++)
                ldmatrix_x4(a[mt], a_base + mt * 16 * (RS * 2) + ks * 32);
#pragma unroll
            for (int nt = 0; nt < 4; nt++)
                ldmatrix_x2(bbr[nt], bb0 + nt * 8 * (RS * 2) + ks * 32);
#pragma unroll
            for (int mt = 0; mt < 4; mt++)
#pragma unroll
                for (int nt = 0; nt < 4; nt++)
                    mma_f16(acc[mt][nt], a[mt], bbr[nt]);
        }

        // ---- epilogue (no barrier; overlaps other warps' MMAs) ----
        unsigned long long x2p[4][2];
#pragma unroll
        for (int mt = 0; mt < 4; mt++) {
            x2p[mt][0] = packf2(x2r[mt][0], x2r[mt][0]);
            x2p[mt][1] = packf2(x2r[mt][1], x2r[mt][1]);
        }

        float cslot[4][2];
#pragma unroll
        for (int nt = 0; nt < 4; nt++) { cslot[nt][0] = 1e30f; cslot[nt][1] = 1e30f; }

#pragma unroll
        for (int nt = 0; nt < 4; nt++) {
            unsigned long long y2u = packf2(y2s[nt].x, y2s[nt].y);
#pragma unroll
            for (int mt = 0; mt < 4; mt++) {
                unsigned long long c01 = packf2(acc[mt][nt][0], acc[mt][nt][1]);
                unsigned long long c23 = packf2(acc[mt][nt][2], acc[mt][nt][3]);
                // rows: y2_j - 2*c
                unsigned long long rr01 = ffma2(c01, NEG2PK, y2u);
                unsigned long long rr23 = ffma2(c23, NEG2PK, y2u);
                rmin[mt][0] = fminf(rmin[mt][0], fminf(f2lo(rr01), f2hi(rr01)));
                rmin[mt][1] = fminf(rmin[mt][1], fminf(f2lo(rr23), f2hi(rr23)));
                // cols: x2_i - 2*c
                unsigned long long rc01 = ffma2(c01, NEG2PK, x2p[mt][0]);
                unsigned long long rc23 = ffma2(c23, NEG2PK, x2p[mt][1]);
                cslot[nt][0] = fminf(cslot[nt][0], fminf(f2lo(rc01), f2lo(rc23)));
                cslot[nt][1] = fminf(cslot[nt][1], fminf(f2hi(rc01), f2hi(rc23)));
            }
        }
        // reduce col slots over the r-bits of the lane (lane = 4r + cth)
#pragma unroll
        for (int m = 4; m <= 16; m <<= 1)
#pragma unroll
            for (int nt = 0; nt < 4; nt++) {
                cslot[nt][0] = fminf(cslot[nt][0],
                                     __shfl_xor_sync(0xffffffffu, cslot[nt][0], m));
                cslot[nt][1] = fminf(cslot[nt][1],
                                     __shfl_xor_sync(0xffffffffu, cslot[nt][1], m));
            }
        if (r == 0) {
#pragma unroll
            for (int nt = 0; nt < 4; nt++) {
                int colb = jt * JT + wj * 32 + nt * 8 + 2 * cth;
                float d0 = fmaxf(y2s[nt].x + cslot[nt][0], 0.f);
                float d1 = fmaxf(y2s[nt].y + cslot[nt][1], 0.f);
                atomicMin(colg + colb,     __float_as_uint(d0));
                atomicMin(colg + colb + 1, __float_as_uint(d1));
            }
        }
    }

    // ---- rowmin finalize ----
#pragma unroll
    for (int mt = 0; mt < 4; mt++)
#pragma unroll
        for (int h = 0; h < 2; h++) {
            float v = rmin[mt][h];
            v = fminf(v, __shfl_xor_sync(0xffffffffu, v, 1));
            v = fminf(v, __shfl_xor_sync(0xffffffffu, v, 2));
            if (cth == 0)
                smem[SROW_F + wid * 64 + mt * 16 + r + h * 8] = v;
        }
    __syncthreads();
    if (tid < JT) {
        int wi2 = tid >> 6, rl = tid & 63;
        float m =          smem[SROW_F + (wi2 * 4 + 0) * 64 + rl];
        m = fminf(m, smem[SROW_F + (wi2 * 4 + 1) * 64 + rl]);
        m = fminf(m, smem[SROW_F + (wi2 * 4 + 2) * 64 + rl]);
        m = fminf(m, smem[SROW_F + (wi2 * 4 + 3) * 64 + rl]);
        size_t row = (size_t)b * NN + (size_t)it * JT + wi2 * 64 + rl;
        float d2 = fmaxf(g_x2[row] + m, 0.f);
        atomicMin(&g_rowmin[row], __float_as_uint(d2));
    }
}

// ---------------- final reduction (parallel, deterministic) ----------------
__global__ void partial_kernel() {
    __shared__ float red[256];
    const int tid = threadIdx.x, blk = blockIdx.x;
    float s = 0.f;
#pragma unroll
    for (int q = 0; q < 4; q++) {
        int i = blk * 1024 + q * 256 + tid;
        if (i < BB * NN) s += sqrtf(__uint_as_float(g_rowmin[i]));
        else s += sqrtf(__uint_as_float(g_colmin[i - BB * NN]));
    }
    red[tid] = s;
    __syncthreads();
    for (int off = 128; off > 0; off >>= 1) {
        if (tid < off) red[tid] += red[tid + off];
        __syncthreads();
    }
    if (tid == 0) g_partial[blk] = red[0];
}

__global__ void final_kernel(float* __restrict__ out) {
    __shared__ float red[128];
    int tid = threadIdx.x;
    red[tid] = g_partial[tid];
    __syncthreads();
    for (int off = 64; off > 0; off >>= 1) {
        if (tid < off) red[tid] += red[tid + off];
        __syncthreads();
    }
    if (tid == 0) out[0] = red[0] / ((float)BB * (float)MM);
}

extern "C" void kernel_launch(void* const* d_in, const int* in_sizes, int n_in,
                              void* d_out, int out_size) {
    const float* x = (const float*)d_in[0];
    const float* y = (const float*)d_in[1];
    float* out = (float*)d_out;

    cudaFuncSetAttribute(chamfer_mma_kernel,
                         cudaFuncAttributeMaxDynamicSharedMemorySize, SMEM_BYTES);

    prep_y_kernel<<<(BB * MM + 255) / 256, 256>>>(y);
    prep_x_kernel<<<(BB * NN + 255) / 256, 256>>>(x);
    chamfer_mma_kernel<<<dim3(NN / JT, BB, NJT / JQ), NTH, SMEM_BYTES>>>();
    partial_kernel<<<128, 256>>>();
    final_kernel<<<1, 128>>>(out);
}